// round 7
// baseline (speedup 1.0000x reference)
#include <cuda_runtime.h>
#include <math.h>

#define SR_F        48000.0f
#define SOUND_SPEED 343.0f
#define MAX_ORDER   10
#define RIR_LEN     24000
#define TAPS        81
#define HALF        40
#define AXN         42            // axis-image table size (2*(2*10+1))
#define NVALID      1561          // #(ax,ay,az) triples with tot_order <= 10 (exact)
#define MAXB        8
#define TILE        512           // output samples per tile
#define TPB         47            // tiles per batch: ceil(24000/512)
#define CAP         1568          // >= NVALID, so overflow is impossible

// ---------------------------------------------------------------------------
// Compile-time table of valid axis-index triples (tot_order <= MAX_ORDER),
// packed as ax + 42*ay + 42*42*az. Batch-independent.
// ---------------------------------------------------------------------------
constexpr int axis_order_ct(int a) {
    int p = (a >= 21) ? 1 : 0;
    int n = a - 21 * p - 10;
    int o1 = n - p; if (o1 < 0) o1 = -o1;
    int o2 = n;     if (o2 < 0) o2 = -o2;
    return o1 + o2;
}

struct ValidTable {
    int v[NVALID];
    constexpr ValidTable() : v() {
        int ord[AXN] = {};
        for (int a = 0; a < AXN; ++a) ord[a] = axis_order_ct(a);
        int s = 0;
        for (int az = 0; az < AXN; ++az)
            for (int ay = 0; ay < AXN; ++ay)
                for (int ax = 0; ax < AXN; ++ax)
                    if (ord[ax] + ord[ay] + ord[az] <= MAX_ORDER)
                        v[s++] = ax + AXN * ay + AXN * AXN * az;
    }
};

__device__ const ValidTable VT = ValidTable();

__device__ float2 g_tab[TAPS];                    // {cos,sin}(pi*k/41)
__device__ int    g_cnt[MAXB * TPB];              // per-tile record counts
__device__ float4 g_list[(long long)MAXB * TPB * CAP * 2];  // 2 x float4 per entry

__constant__ float BETA_POW[11] = {
    1.0f, 0.9f, 0.81f, 0.729f, 0.6561f, 0.59049f,
    0.531441f, 0.4782969f, 0.43046721f, 0.387420489f, 0.3486784401f
};

__device__ __forceinline__ void decode_axis(int a, float& sign, float& off, int& order)
{
    int p = (a >= 21) ? 1 : 0;
    int n = a - 21 * p - 10;
    sign  = (float)(1 - 2 * p);
    off   = (float)(2 * n);
    order = abs(n - p) + abs(n);
}

// ---------------------------------------------------------------------------
// Kernel 1: build records + bin them into per-(batch,tile) lists.
// Also writes g_tab and origin. Requires g_cnt == 0 on entry (zeroed at
// module load; tile_kernel re-zeros after consuming -> replay-safe).
// d_out layout: [B*RIR_LEN floats rir][B floats origin]
// ---------------------------------------------------------------------------
__global__ void __launch_bounds__(256)
bin_kernel(const float* __restrict__ in, float* __restrict__ out, int B, int nrec)
{
    int i = blockIdx.x * blockDim.x + threadIdx.x;

    if (i < TAPS) {
        float a = (float)i * (1.0f / 41.0f);
        g_tab[i] = make_float2(cospif(a), sinpif(a));
    }
    if (i < B) {
        const float* row = in + i * 9;
        float rx = row[0] * 10.0f, ry = row[1] * 10.0f, rz = row[2] * 10.0f;
        float dx = (row[3] - row[6]) * rx;
        float dy = (row[4] - row[7]) * ry;
        float dz = (row[5] - row[8]) * rz;
        out[B * RIR_LEN + i] =
            40.0f + SR_F * sqrtf(dx * dx + dy * dy + dz * dz) / SOUND_SPEED;
    }
    if (i >= nrec) return;

    int b = i / NVALID;
    int s = i - b * NVALID;
    int img = VT.v[s];
    int ax = img % AXN;
    int ay = (img / AXN) % AXN;
    int az = img / (AXN * AXN);

    float sgx, ofx; int ox; decode_axis(ax, sgx, ofx, ox);
    float sgy, ofy; int oy; decode_axis(ay, sgy, ofy, oy);
    float sgz, ofz; int oz; decode_axis(az, sgz, ofz, oz);

    const float* row = in + b * 9;
    float rx = row[0] * 10.0f, ry = row[1] * 10.0f, rz = row[2] * 10.0f;
    float mx = row[3] * rx,    my = row[4] * ry,    mz = row[5] * rz;
    float sx = row[6] * rx,    sy = row[7] * ry,    sz = row[8] * rz;

    float dx = sgx * sx + ofx * rx - mx;
    float dy = sgy * sy + ofy * ry - my;
    float dz = sgz * sz + ofz * rz - mz;

    float dist = sqrtf(dx * dx + dy * dy + dz * dz);
    float tau  = SR_F * dist / SOUND_SPEED;
    float i0   = floorf(tau);
    float frac = tau - i0;

    int base = (int)i0 + HALF;            // first tap's sample index (>= 40)
    if (base >= RIR_LEN) return;          // contributes nothing

    const float INV_PI = 0.318309886183790672f;
    float amp = BETA_POW[ox + oy + oz] / (4.0f * 3.14159265358979323846f * dist);
    float c   = amp * sinpif(frac) * INV_PI;
    float bb  = (40.0f + frac) * (1.0f / 41.0f);
    float cw  = cospif(bb);
    float sw  = sinpif(bb);

    float4 e0 = make_float4(__int_as_float(base), frac, amp, c);
    float4 e1 = make_float4(cw, sw, 0.0f, 0.0f);

    int tb = b * TPB;
    int t0 = base >> 9;                               // TILE = 512
    int s0 = atomicAdd(&g_cnt[tb + t0], 1);
    long long idx0 = ((long long)(tb + t0) * CAP + s0) * 2;
    g_list[idx0]     = e0;
    g_list[idx0 + 1] = e1;

    int t1 = (base + TAPS - 1) >> 9;
    if (t1 != t0 && t1 < TPB) {
        int s1 = atomicAdd(&g_cnt[tb + t1], 1);
        long long idx1 = ((long long)(tb + t1) * CAP + s1) * 2;
        g_list[idx1]     = e0;
        g_list[idx1 + 1] = e1;
    }
}

// ---------------------------------------------------------------------------
// Kernel 2: one block per (batch,tile). Each thread owns 4 consecutive
// output samples in registers; scans the tile's record list (staged through
// smem) and accumulates overlapping taps. Plain coalesced stores -> no
// global atomics, no memset needed. Re-zeros its counter for the next replay.
// ---------------------------------------------------------------------------
__global__ void __launch_bounds__(128)
tile_kernel(float* __restrict__ out, int B)
{
    int t  = blockIdx.x;                 // 0 .. B*TPB-1
    int b  = t / TPB;
    int tl = t - b * TPB;
    int tstart = tl * TILE;              // batch-local start sample of tile
    int tid = threadIdx.x;

    __shared__ int    s_n;
    __shared__ float2 s_tab[TAPS];
    __shared__ float4 s_rec[128 * 2];

    if (tid == 0) { s_n = g_cnt[t]; g_cnt[t] = 0; }
    for (int k = tid; k < TAPS; k += 128) s_tab[k] = g_tab[k];
    __syncthreads();

    int n = s_n;
    if (n > CAP) n = CAP;                // provably never triggers

    float acc[4] = {0.f, 0.f, 0.f, 0.f};
    int j4 = tid * 4;                    // tile-local first sample this thread owns

    for (int ch = 0; ch < n; ch += 128) {
        int m = n - ch; if (m > 128) m = 128;
        if (ch) __syncthreads();
        if (tid < m) {
            long long idx = ((long long)t * CAP + ch + tid) * 2;
            s_rec[tid * 2]     = g_list[idx];
            s_rec[tid * 2 + 1] = g_list[idx + 1];
        }
        __syncthreads();

        for (int r = 0; r < m; ++r) {
            float4 r0 = s_rec[r * 2];                       // smem broadcast
            int base_l = __float_as_int(r0.x) - tstart;     // in [-80, TILE-1]
            if (j4 + 3 < base_l || j4 > base_l + (TAPS - 1)) continue;
            float4 r1 = s_rec[r * 2 + 1];
            float frac = r0.y, amp = r0.z, c = r0.w;
            float cw = r1.x, sw = r1.y;

            #pragma unroll
            for (int k = 0; k < 4; ++k) {
                int tap = j4 + k - base_l;
                if (tap < 0 || tap >= TAPS) continue;
                float tt = (float)(tap - HALF) - frac;
                float v;
                if (tt == 0.0f) v = amp;                    // tap==40 && frac==0
                else            v = __fdividef((tap & 1) ? c : -c, tt);
                if (tap == 0 && frac > 0.0f) v = 0.0f;      // |t| > HALF
                float2 cs = s_tab[tap];
                float win = 0.5f + 0.5f * fmaf(cs.x, cw, cs.y * sw);
                acc[k] += v * win;
            }
        }
    }

    int gl = tstart + j4;                // batch-local sample index
    float* dst = out + b * RIR_LEN + gl;
    if (gl + 3 < RIR_LEN) {
        ((float4*)dst)[0] = make_float4(acc[0], acc[1], acc[2], acc[3]);
    } else {
        #pragma unroll
        for (int k = 0; k < 4; ++k)
            if (gl + k < RIR_LEN) dst[k] = acc[k];
    }
}

extern "C" void kernel_launch(void* const* d_in, const int* in_sizes, int n_in,
                              void* d_out, int out_size)
{
    const float* in = (const float*)d_in[0];
    float* out = (float*)d_out;
    int B = in_sizes[0] / 9;
    if (B > MAXB) B = MAXB;

    int nrec = B * NVALID;
    bin_kernel<<<(nrec + 255) / 256, 256>>>(in, out, B, nrec);

    tile_kernel<<<B * TPB, 128>>>(out, B);
}

// round 8
// speedup vs baseline: 10.5670x; 10.5670x over previous
#include <cuda_runtime.h>
#include <math.h>

#define SR_F        48000.0f
#define SOUND_SPEED 343.0f
#define MAX_ORDER   10
#define RIR_LEN     24000
#define TAPS        81
#define HALF        40
#define AXN         42            // axis-image table size (2*(2*10+1))
#define NVALID      1561          // #(ax,ay,az) triples with tot_order <= 10 (exact)
#define MAXB        8
#define RPW         4             // records per warp

// ---------------------------------------------------------------------------
// Compile-time table of valid axis-index triples (tot_order <= MAX_ORDER),
// packed as ax + 42*ay + 42*42*az. Batch-independent.
// ---------------------------------------------------------------------------
constexpr int axis_order_ct(int a) {
    int p = (a >= 21) ? 1 : 0;
    int n = a - 21 * p - 10;
    int o1 = n - p; if (o1 < 0) o1 = -o1;
    int o2 = n;     if (o2 < 0) o2 = -o2;
    return o1 + o2;
}

struct ValidTable {
    int v[NVALID];
    constexpr ValidTable() : v() {
        int ord[AXN] = {};
        for (int a = 0; a < AXN; ++a) ord[a] = axis_order_ct(a);
        int s = 0;
        for (int az = 0; az < AXN; ++az)
            for (int ay = 0; ay < AXN; ++ay)
                for (int ax = 0; ax < AXN; ++ax)
                    if (ord[ax] + ord[ay] + ord[az] <= MAX_ORDER)
                        v[s++] = ax + AXN * ay + AXN * AXN * az;
    }
};

__device__ const ValidTable VT = ValidTable();

// Scratch RIR accumulator. Zero at module load; copy_kernel re-zeroes it each
// replay, so every kernel_launch call sees it zeroed.
__device__ float g_scr[MAXB * RIR_LEN];

__constant__ float BETA_POW[11] = {
    1.0f, 0.9f, 0.81f, 0.729f, 0.6561f, 0.59049f,
    0.531441f, 0.4782969f, 0.43046721f, 0.387420489f, 0.3486784401f
};

__device__ __forceinline__ void decode_axis(int a, float& sign, float& off, int& order)
{
    int p = (a >= 21) ? 1 : 0;
    int n = a - 21 * p - 10;
    sign  = (float)(1 - 2 * p);
    off   = (float)(2 * n);
    order = abs(n - p) + abs(n);
}

// ---------------------------------------------------------------------------
// Kernel 1: scatter. No dependency on any zeroing pass (targets g_scr).
// Each warp owns RPW consecutive records. Lanes 0..RPW-1 build the records
// (geometry -> 8 floats) into smem; then all 32 lanes scatter taps
// {lane, lane+32, lane+64} per record with per-thread window constants.
// Also writes origin into d_out (plain stores).
// d_out layout: [B*RIR_LEN floats rir][B floats origin]
// ---------------------------------------------------------------------------
__global__ void __launch_bounds__(256)
scatter_kernel(const float* __restrict__ in, float* __restrict__ out,
               int B, int nrec)
{
    const int gtid = blockIdx.x * blockDim.x + threadIdx.x;
    const int w    = gtid >> 5;          // global warp id
    const int wloc = threadIdx.x >> 5;   // warp within block (0..7)
    const int lane = threadIdx.x & 31;
    const int rec0 = w * RPW;

    __shared__ float4 s_rec[8][RPW][2];  // 8 warps x RPW records x 32B

    // Origin (8 values) — independent of everything else.
    if (gtid < B) {
        const float* row = in + gtid * 9;
        float rx = row[0] * 10.0f, ry = row[1] * 10.0f, rz = row[2] * 10.0f;
        float dx = (row[3] - row[6]) * rx;
        float dy = (row[4] - row[7]) * ry;
        float dz = (row[5] - row[8]) * rz;
        out[B * RIR_LEN + gtid] =
            40.0f + SR_F * sqrtf(dx * dx + dy * dy + dz * dz) / SOUND_SPEED;
    }

    if (rec0 >= nrec) return;

    // ---- Build phase: lanes 0..RPW-1 each build one record ----
    if (lane < RPW && rec0 + lane < nrec) {
        int i = rec0 + lane;
        int b = i / NVALID;
        int s = i - b * NVALID;
        int img = VT.v[s];
        int ax = img % AXN;
        int ay = (img / AXN) % AXN;
        int az = img / (AXN * AXN);

        float sgx, ofx; int ox; decode_axis(ax, sgx, ofx, ox);
        float sgy, ofy; int oy; decode_axis(ay, sgy, ofy, oy);
        float sgz, ofz; int oz; decode_axis(az, sgz, ofz, oz);

        const float* row = in + b * 9;
        float rx = row[0] * 10.0f, ry = row[1] * 10.0f, rz = row[2] * 10.0f;
        float mx = row[3] * rx,    my = row[4] * ry,    mz = row[5] * rz;
        float sx = row[6] * rx,    sy = row[7] * ry,    sz = row[8] * rz;

        float dx = sgx * sx + ofx * rx - mx;
        float dy = sgy * sy + ofy * ry - my;
        float dz = sgz * sz + ofz * rz - mz;

        float dist = sqrtf(dx * dx + dy * dy + dz * dz);
        float tau  = SR_F * dist / SOUND_SPEED;
        float i0   = floorf(tau);
        float frac = tau - i0;

        const float INV_PI = 0.318309886183790672f;
        int  bofs  = b * RIR_LEN;
        int  end_g = bofs + RIR_LEN;
        int  base  = (int)i0 + HALF;
        int  base_g = (base >= RIR_LEN) ? end_g : bofs + base;
        float amp = BETA_POW[ox + oy + oz] / (4.0f * 3.14159265358979323846f * dist);
        float c   = amp * sinpif(frac) * INV_PI;
        float bb  = (40.0f + frac) * (1.0f / 41.0f);
        float cw, sw;
        sincospif(bb, &sw, &cw);

        s_rec[wloc][lane][0] = make_float4(__int_as_float(base_g), frac, amp, c);
        s_rec[wloc][lane][1] = make_float4(cw, sw, __int_as_float(end_g), 0.0f);
    }
    __syncwarp();

    // ---- Per-thread constants (amortized over RPW records) ----
    // taps handled by this thread: lane, lane+32, lane+64 (if < 81)
    float ct[3], st[3];
    #pragma unroll
    for (int k = 0; k < 3; ++k) {
        float a = (float)(lane + 32 * k) * (1.0f / 41.0f);
        sincospif(a, &st[k], &ct[k]);
    }
    const float A0 = (float)(lane - HALF);           // tap - 40 for k=0
    const float sgn = (lane & 1) ? 1.0f : -1.0f;     // sinc sign, parity of tap

    int nr = nrec - rec0; if (nr > RPW) nr = RPW;

    for (int j = 0; j < nr; ++j) {
        float4 r0 = s_rec[wloc][j][0];
        float4 r1 = s_rec[wloc][j][1];
        int   base_g = __float_as_int(r0.x);
        float frac   = r0.y;
        float amp    = r0.z;
        float cc     = r0.w * sgn;       // signed numerator
        float cw     = r1.x;
        float sw     = r1.y;
        int   end_g  = __float_as_int(r1.z);

        #pragma unroll
        for (int k = 0; k < 3; ++k) {
            int tap = lane + 32 * k;
            if (k == 2 && lane > 16) break;          // tap >= 81
            int idx = base_g + tap;
            if (idx >= end_g) continue;

            float t = (A0 + (float)(32 * k)) - frac;
            float v;
            if (t == 0.0f) v = amp;                  // tap==40 && frac==0
            else           v = __fdividef(cc, t);
            if (tap == 0 && frac > 0.0f) v = 0.0f;   // |t| > HALF support edge

            float win = 0.5f + 0.5f * fmaf(ct[k], cw, st[k] * sw);
            atomicAdd(&g_scr[idx], v * win);
        }
    }
}

// ---------------------------------------------------------------------------
// Kernel 2: copy scratch -> d_out and clear scratch for the next replay.
// Pure float4 bandwidth; no atomics.
// ---------------------------------------------------------------------------
__global__ void __launch_bounds__(256)
copy_kernel(float* __restrict__ out, int n4)
{
    int i = blockIdx.x * blockDim.x + threadIdx.x;
    if (i >= n4) return;
    float4* scr4 = (float4*)g_scr;
    float4 v = scr4[i];
    ((float4*)out)[i] = v;
    scr4[i] = make_float4(0.f, 0.f, 0.f, 0.f);
}

extern "C" void kernel_launch(void* const* d_in, const int* in_sizes, int n_in,
                              void* d_out, int out_size)
{
    const float* in = (const float*)d_in[0];
    float* out = (float*)d_out;
    int B = in_sizes[0] / 9;
    if (B > MAXB) B = MAXB;

    int nrec   = B * NVALID;                       // 12488
    int nwarps = (nrec + RPW - 1) / RPW;           // 3122
    int blocks = (nwarps * 32 + 255) / 256;        // 391

    scatter_kernel<<<blocks, 256>>>(in, out, B, nrec);

    int n4 = B * (RIR_LEN / 4);                    // 48000 float4s
    copy_kernel<<<(n4 + 255) / 256, 256>>>(out, n4);
}